// round 10
// baseline (speedup 1.0000x reference)
#include <cuda_runtime.h>
#include <cuda_bf16.h>
#include <mma.h>
#include <math.h>
#include <stdint.h>

using namespace nvcuda;

#define WINN 4
#define LTOK 36

// Dynamic conv weights, bf16 hi/lo, layout [w*9+p][ic(64)][oc stride 72]
#define WROW 72
__device__ __nv_bfloat16 g_Whi[36 * 64 * WROW];
__device__ __nv_bfloat16 g_Wlo[36 * 64 * WROW];

// Pre-converted input, channel-last bf16 hi/lo: [b][y][x][c=64]
__device__ __nv_bfloat16 g_xhi[8 * 256 * 256 * 64];
__device__ __nv_bfloat16 g_xlo[8 * 256 * 256 * 64];

// ===========================================================================
// Stage 0: convert x fp32 [b][c][y][x] -> channel-last bf16 hi/lo [b][y][x][c]
// Block = one (b, y) row, 256 threads = x. Coalesced reads per c; each thread
// writes its own 128B hi + 128B lo span.
// ===========================================================================
__global__ __launch_bounds__(256) void stage0_kernel(const float* __restrict__ x)
{
    const int xq = threadIdx.x;
    const int y  = blockIdx.x & 255;
    const int b  = blockIdx.x >> 8;
    const float* src = x + (size_t)b * (64 * 65536) + y * 256 + xq;

    __nv_bfloat16 hi[64], lo[64];
    #pragma unroll
    for (int c = 0; c < 64; c++) {
        float v = src[(size_t)c * 65536];
        __nv_bfloat16 h = __float2bfloat16(v);
        hi[c] = h;
        lo[c] = __float2bfloat16(v - __bfloat162float(h));
    }
    size_t o = ((size_t)(b * 256 + y) * 256 + xq) * 64;
    uint4* dh = (uint4*)(g_xhi + o);
    uint4* dl = (uint4*)(g_xlo + o);
    #pragma unroll
    for (int q = 0; q < 8; q++) {
        dh[q] = ((const uint4*)hi)[q];
        dl[q] = ((const uint4*)lo)[q];
    }
}

// ===========================================================================
// Stage 1: build dynamic conv kernels (one block per oc b = blockIdx.x).
// ===========================================================================
#define SQ_STRIDE 193
#define SA_STRIDE 65
#define SK_STRIDE 65

__global__ __launch_bounds__(288) void stage1_kernel(
    const float* __restrict__ conv_w, const float* __restrict__ w_qkv,
    const float* __restrict__ b_qkv,  const float* __restrict__ w_out,
    const float* __restrict__ b_out,  const float* __restrict__ se_w1,
    const float* __restrict__ se_b1,  const float* __restrict__ se_w2,
    const float* __restrict__ se_b2)
{
    const int b   = blockIdx.x;
    const int tid = threadIdx.x;

    __shared__ float sA[LTOK * SA_STRIDE];
    __shared__ float sQ[LTOK * SQ_STRIDE];
    __shared__ float pooled[4][64];
    __shared__ float hr[4][4];

    for (int t = tid; t < LTOK * 64; t += 288) {
        int l = t >> 6, i = t & 63;
        int w = l / 9, p = l - w * 9;
        sA[l * SA_STRIDE + i] = conv_w[(((w * 64 + b) * 64 + i) * 9) + p];
    }
    __syncthreads();

    {
        const int l  = tid % 36;
        const int j0 = tid / 36;
        const float* kr = sA + l * SA_STRIDE;
        for (int k = 0; k < 24; k++) {
            int j = j0 + 8 * k;
            float acc = b_qkv[j];
            const float* wr = w_qkv + j * 64;
            #pragma unroll
            for (int i = 0; i < 64; i++) acc = fmaf(kr[i], wr[i], acc);
            sQ[l * SQ_STRIDE + j] = acc;
        }
    }
    __syncthreads();

    {
        int h = tid / 36, l = tid - h * 36;
        const int qo = h * 8;
        const float scale = 0.35355339059327373f;
        float qv[8];
        #pragma unroll
        for (int d = 0; d < 8; d++) qv[d] = sQ[l * SQ_STRIDE + qo + d] * scale;

        float sc[36];
        float mx = -1e30f;
        for (int m = 0; m < 36; m++) {
            float s = 0.f;
            #pragma unroll
            for (int d = 0; d < 8; d++)
                s = fmaf(qv[d], sQ[m * SQ_STRIDE + 64 + qo + d], s);
            sc[m] = s;
            mx = fmaxf(mx, s);
        }
        float sum = 0.f;
        for (int m = 0; m < 36; m++) { float e = expf(sc[m] - mx); sc[m] = e; sum += e; }
        float inv = 1.f / sum;
        float o[8];
        #pragma unroll
        for (int d = 0; d < 8; d++) o[d] = 0.f;
        for (int m = 0; m < 36; m++) {
            float a = sc[m];
            #pragma unroll
            for (int d = 0; d < 8; d++)
                o[d] = fmaf(a, sQ[m * SQ_STRIDE + 128 + qo + d], o[d]);
        }
        #pragma unroll
        for (int d = 0; d < 8; d++) sA[l * SA_STRIDE + qo + d] = o[d] * inv;
    }
    __syncthreads();

    {
        const int l  = tid % 36;
        const int j0 = tid / 36;
        const float* orow = sA + l * SA_STRIDE;
        for (int k = 0; k < 8; k++) {
            int j = j0 + 8 * k;
            float acc = b_out[j];
            const float* wr = w_out + j * 64;
            #pragma unroll
            for (int i = 0; i < 64; i++) acc = fmaf(orow[i], wr[i], acc);
            sQ[l * SK_STRIDE + j] = acc;
        }
    }
    __syncthreads();

    if (tid < 256) {
        int w = tid >> 6, i = tid & 63;
        float s = 0.f;
        #pragma unroll
        for (int p = 0; p < 9; p++) s += sQ[(w * 9 + p) * SK_STRIDE + i];
        pooled[w][i] = s * (1.f / 9.f);
    }
    __syncthreads();
    if (tid < 16) {
        int w = tid >> 2, r = tid & 3;
        float acc = se_b1[w * 4 + r];
        #pragma unroll
        for (int i = 0; i < 64; i++)
            acc = fmaf(pooled[w][i], se_w1[(w * 4 + r) * 64 + i], acc);
        hr[w][r] = fmaxf(acc, 0.f);
    }
    __syncthreads();
    if (tid < 256) {
        int w = tid >> 6, i = tid & 63;   // i = ic
        float acc = se_b2[w * 64 + i];
        #pragma unroll
        for (int r = 0; r < 4; r++)
            acc = fmaf(hr[w][r], se_w2[(w * 64 + i) * 4 + r], acc);
        float g = 1.f / (1.f + expf(-acc));
        #pragma unroll
        for (int p = 0; p < 9; p++) {
            float v = sQ[(w * 9 + p) * SK_STRIDE + i] * g;
            __nv_bfloat16 hi = __float2bfloat16(v);
            __nv_bfloat16 lo = __float2bfloat16(v - __bfloat162float(hi));
            int idx = ((w * 9 + p) * 64 + i) * WROW + b;
            g_Whi[idx] = hi;
            g_Wlo[idx] = lo;
        }
    }
}

// ===========================================================================
// Stage 2: WMMA bf16-split implicit-GEMM conv + LN + residual.
// CTA = one 16x16 px tile. 256 threads = 8 warps, 2 CTAs/SM.
// K = 4 chunks of 16 ic, 9 taps. Warp = 2 image rows x 64 oc.
// A staged from pre-converted channel-last bf16 globals: pure uint4 copies.
// A halo smem: [18*18 pos][24] (16 ic + 8 pad), lda = 24 elems (48B)
// W smem:      [9 taps][16 ic][72 oc], ldb = 72 elems (144B)
// Epilogue D:  stride 68 floats (272B = 17*16B — wmma ldm contract).
// ===========================================================================
#define ALDA   24
#define A_ELEMS (18 * 18 * ALDA)                 // 7776 bf16 per buffer
#define W_ELEMS (9 * 16 * WROW)                  // 10368 bf16 per buffer
#define AHI_E  0
#define ALO_E  (A_ELEMS)
#define WHI_E  (2 * A_ELEMS)
#define WLO_E  (2 * A_ELEMS + W_ELEMS)
#define SMEM2_BYTES ((2 * A_ELEMS + 2 * W_ELEMS) * 2)   // 72576 B
#define DSTRIDE 68

typedef wmma::fragment<wmma::matrix_a, 16, 16, 16, __nv_bfloat16, wmma::row_major> FragA;
typedef wmma::fragment<wmma::matrix_b, 16, 16, 16, __nv_bfloat16, wmma::row_major> FragB;
typedef wmma::fragment<wmma::accumulator, 16, 16, 16, float> FragC;

__global__ __launch_bounds__(256, 2) void stage2_kernel(
    const float* __restrict__ x, const float* __restrict__ ln_w,
    const float* __restrict__ ln_b, float* __restrict__ out)
{
    extern __shared__ __nv_bfloat16 sb[];
    __nv_bfloat16* Ahi = sb + AHI_E;
    __nv_bfloat16* Alo = sb + ALO_E;
    __nv_bfloat16* Whi = sb + WHI_E;
    __nv_bfloat16* Wlo = sb + WLO_E;

    const int blk  = blockIdx.x;
    const int tile = blk & 63;
    const int w    = (blk >> 6) & 3;
    const int b    = blk >> 8;
    const int ty0  = (tile >> 3) << 4;
    const int tx0  = (tile & 7) << 4;
    const int wh   = w >> 1, ww = w & 1;

    const int tid = threadIdx.x;
    const int wid = tid >> 5;

    FragC acc[2][4];
    #pragma unroll
    for (int r = 0; r < 2; r++)
        #pragma unroll
        for (int n = 0; n < 4; n++) wmma::fill_fragment(acc[r][n], 0.f);

    #pragma unroll 1
    for (int c = 0; c < 4; c++) {
        const int ic0 = c * 16;
        // ---- stage A halo: uint4 copies from pre-converted bf16 globals ----
        // t encodes: quad (which 16B of the 32B ic-span), hl (hi/lo), pos
        for (int t = tid; t < 1296; t += 256) {
            int quad = t & 1;
            int hl   = (t >> 1) & 1;
            int pos  = t >> 2;
            int hrow = pos / 18, hcol = pos - hrow * 18;
            int ly = ty0 + hrow - 1, lx = tx0 + hcol - 1;
            uint4 v = make_uint4(0u, 0u, 0u, 0u);
            if (ly >= 0 && ly < 128 && lx >= 0 && lx < 128) {
                size_t go = ((size_t)(b * 256 + wh * 128 + ly) * 256
                             + ww * 128 + lx) * 64 + ic0 + quad * 8;
                v = *(const uint4*)((hl ? g_xlo : g_xhi) + go);
            }
            *(uint4*)((hl ? Alo : Ahi) + pos * ALDA + quad * 8) = v;
        }
        // ---- stage W chunk: 9 taps x 16 ic rows x 72 oc, uint4 copies ----
        for (int t = tid; t < 1296; t += 256) {           // 1296 = 9*16*9
            int tap = t / 144, rem = t - tap * 144;       // rem: 16 rows x 9 uint4
            int row = rem / 9, q = rem - row * 9;
            size_t so = (size_t)((w * 9 + tap) * 64 + ic0 + row) * WROW + q * 8;
            int   dof = (tap * 16 + row) * WROW + q * 8;
            *(uint4*)(Whi + dof) = *(const uint4*)(g_Whi + so);
            *(uint4*)(Wlo + dof) = *(const uint4*)(g_Wlo + so);
        }
        __syncthreads();

        // ---- mainloop: 9 taps, one 16-ic k-step each ----
        #pragma unroll 1
        for (int tap = 0; tap < 9; tap++) {
            const int dy = tap / 3, dx = tap - 3 * (tap / 3);
            FragB bh[4], bl[4];
            const __nv_bfloat16* wbh = Whi + tap * 16 * WROW;
            const __nv_bfloat16* wbl = Wlo + tap * 16 * WROW;
            #pragma unroll
            for (int n = 0; n < 4; n++) {
                wmma::load_matrix_sync(bh[n], wbh + n * 16, WROW);
                wmma::load_matrix_sync(bl[n], wbl + n * 16, WROW);
            }
            #pragma unroll
            for (int r = 0; r < 2; r++) {
                const int yrow = wid * 2 + r;
                const int aoff = ((yrow + dy) * 18 + dx) * ALDA;
                FragA ah, al;
                wmma::load_matrix_sync(ah, Ahi + aoff, ALDA);
                wmma::load_matrix_sync(al, Alo + aoff, ALDA);
                #pragma unroll
                for (int n = 0; n < 4; n++) {
                    wmma::mma_sync(acc[r][n], ah, bh[n], acc[r][n]);
                    wmma::mma_sync(acc[r][n], al, bh[n], acc[r][n]);
                    wmma::mma_sync(acc[r][n], ah, bl[n], acc[r][n]);
                }
            }
        }
        __syncthreads();
    }

    // ---- epilogue: dump to smem, LN over oc, residual, store ----
    float* D = (float*)sb;                           // [256 px][68]
    #pragma unroll
    for (int r = 0; r < 2; r++) {
        const int yrow = wid * 2 + r;
        #pragma unroll
        for (int n = 0; n < 4; n++)
            wmma::store_matrix_sync(D + (yrow * 16) * DSTRIDE + n * 16,
                                    acc[r][n], DSTRIDE, wmma::mem_row_major);
    }
    __syncthreads();

    {
        const int y  = tid >> 4, xq = tid & 15;
        const float* drow = D + tid * DSTRIDE;
        float s = 0.f, sq = 0.f;
        #pragma unroll
        for (int oc = 0; oc < 64; oc++) {
            float d = drow[oc];
            s += d;
            sq = fmaf(d, d, sq);
        }
        float mu   = s * (1.f / 64.f);
        float rstd = rsqrtf(sq * (1.f / 64.f) - mu * mu + 1e-5f);
        const int gy = wh * 128 + ty0 + y;
        const int gx = ww * 128 + tx0 + xq;
        #pragma unroll 4
        for (int oc = 0; oc < 64; oc++) {
            size_t gi = ((size_t)(b * 64 + oc) * 256 + gy) * 256 + gx;
            out[gi] = x[gi] + (drow[oc] - mu) * rstd * ln_w[oc] + ln_b[oc];
        }
    }
}

// ===========================================================================
extern "C" void kernel_launch(void* const* d_in, const int* in_sizes, int n_in,
                              void* d_out, int out_size)
{
    (void)in_sizes; (void)n_in; (void)out_size;
    const float* x      = (const float*)d_in[0];
    const float* conv_w = (const float*)d_in[1];
    const float* w_qkv  = (const float*)d_in[2];
    const float* b_qkv  = (const float*)d_in[3];
    const float* w_out  = (const float*)d_in[4];
    const float* b_out  = (const float*)d_in[5];
    const float* se_w1  = (const float*)d_in[6];
    const float* se_b1  = (const float*)d_in[7];
    const float* se_w2  = (const float*)d_in[8];
    const float* se_b2  = (const float*)d_in[9];
    const float* ln_w   = (const float*)d_in[10];
    const float* ln_b   = (const float*)d_in[11];
    float* out = (float*)d_out;

    cudaFuncSetAttribute(stage2_kernel,
                         cudaFuncAttributeMaxDynamicSharedMemorySize, SMEM2_BYTES);

    stage0_kernel<<<2048, 256>>>(x);
    stage1_kernel<<<64, 288>>>(conv_w, w_qkv, b_qkv, w_out, b_out,
                               se_w1, se_b1, se_w2, se_b2);
    stage2_kernel<<<2048, 256, SMEM2_BYTES>>>(x, ln_w, ln_b, out);
}

// round 11
// speedup vs baseline: 1.0460x; 1.0460x over previous
#include <cuda_runtime.h>
#include <cuda_bf16.h>
#include <mma.h>
#include <math.h>
#include <stdint.h>

using namespace nvcuda;

#define WINN 4
#define LTOK 36

// Dynamic conv weights, bf16 hi/lo, layout [w*9+p][ic(64)][oc stride 72]
#define WROW 72
__device__ __nv_bfloat16 g_Whi[36 * 64 * WROW];
__device__ __nv_bfloat16 g_Wlo[36 * 64 * WROW];

// Pre-converted input, channel-last bf16 hi/lo: [b][y][x][c=64]
__device__ __nv_bfloat16 g_xhi[8 * 256 * 256 * 64];
__device__ __nv_bfloat16 g_xlo[8 * 256 * 256 * 64];

__device__ __forceinline__ uint32_t smem_u32(const void* p) {
    uint32_t a;
    asm("{ .reg .u64 t; cvta.to.shared.u64 t, %1; cvt.u32.u64 %0, t; }" : "=r"(a) : "l"(p));
    return a;
}
__device__ __forceinline__ void cp16(uint32_t dst, const void* src, bool valid) {
    int sz = valid ? 16 : 0;
    asm volatile("cp.async.cg.shared.global [%0], [%1], 16, %2;\n"
                 :: "r"(dst), "l"(src), "r"(sz) : "memory");
}
#define CP_COMMIT() asm volatile("cp.async.commit_group;\n" ::: "memory")
#define CP_WAIT0()  asm volatile("cp.async.wait_group 0;\n" ::: "memory")

// ===========================================================================
// Stage 0: x fp32 [b][c][y][x] -> channel-last bf16 hi/lo [b][y][x][c].
// 8 channels per pass -> tiny live register set, no spills.
// ===========================================================================
__global__ __launch_bounds__(256) void stage0_kernel(const float* __restrict__ x)
{
    const int xq = threadIdx.x;
    const int y  = blockIdx.x & 255;
    const int b  = blockIdx.x >> 8;
    const float* src = x + (size_t)b * (64 * 65536) + y * 256 + xq;
    const size_t o = ((size_t)(b * 256 + y) * 256 + xq) * 64;

    #pragma unroll
    for (int g = 0; g < 8; g++) {
        __nv_bfloat16 hi[8], lo[8];
        #pragma unroll
        for (int c = 0; c < 8; c++) {
            float v = src[(size_t)(g * 8 + c) * 65536];
            __nv_bfloat16 h = __float2bfloat16(v);
            hi[c] = h;
            lo[c] = __float2bfloat16(v - __bfloat162float(h));
        }
        *(uint4*)(g_xhi + o + g * 8) = *(const uint4*)hi;
        *(uint4*)(g_xlo + o + g * 8) = *(const uint4*)lo;
    }
}

// ===========================================================================
// Stage 1: build dynamic conv kernels (one block per oc b = blockIdx.x).
// ===========================================================================
#define SQ_STRIDE 193
#define SA_STRIDE 65
#define SK_STRIDE 65

__global__ __launch_bounds__(288) void stage1_kernel(
    const float* __restrict__ conv_w, const float* __restrict__ w_qkv,
    const float* __restrict__ b_qkv,  const float* __restrict__ w_out,
    const float* __restrict__ b_out,  const float* __restrict__ se_w1,
    const float* __restrict__ se_b1,  const float* __restrict__ se_w2,
    const float* __restrict__ se_b2)
{
    const int b   = blockIdx.x;
    const int tid = threadIdx.x;

    __shared__ float sA[LTOK * SA_STRIDE];
    __shared__ float sQ[LTOK * SQ_STRIDE];
    __shared__ float pooled[4][64];
    __shared__ float hr[4][4];

    for (int t = tid; t < LTOK * 64; t += 288) {
        int l = t >> 6, i = t & 63;
        int w = l / 9, p = l - w * 9;
        sA[l * SA_STRIDE + i] = conv_w[(((w * 64 + b) * 64 + i) * 9) + p];
    }
    __syncthreads();

    {
        const int l  = tid % 36;
        const int j0 = tid / 36;
        const float* kr = sA + l * SA_STRIDE;
        for (int k = 0; k < 24; k++) {
            int j = j0 + 8 * k;
            float acc = b_qkv[j];
            const float* wr = w_qkv + j * 64;
            #pragma unroll
            for (int i = 0; i < 64; i++) acc = fmaf(kr[i], wr[i], acc);
            sQ[l * SQ_STRIDE + j] = acc;
        }
    }
    __syncthreads();

    {
        int h = tid / 36, l = tid - h * 36;
        const int qo = h * 8;
        const float scale = 0.35355339059327373f;
        float qv[8];
        #pragma unroll
        for (int d = 0; d < 8; d++) qv[d] = sQ[l * SQ_STRIDE + qo + d] * scale;

        float sc[36];
        float mx = -1e30f;
        for (int m = 0; m < 36; m++) {
            float s = 0.f;
            #pragma unroll
            for (int d = 0; d < 8; d++)
                s = fmaf(qv[d], sQ[m * SQ_STRIDE + 64 + qo + d], s);
            sc[m] = s;
            mx = fmaxf(mx, s);
        }
        float sum = 0.f;
        for (int m = 0; m < 36; m++) { float e = expf(sc[m] - mx); sc[m] = e; sum += e; }
        float inv = 1.f / sum;
        float o[8];
        #pragma unroll
        for (int d = 0; d < 8; d++) o[d] = 0.f;
        for (int m = 0; m < 36; m++) {
            float a = sc[m];
            #pragma unroll
            for (int d = 0; d < 8; d++)
                o[d] = fmaf(a, sQ[m * SQ_STRIDE + 128 + qo + d], o[d]);
        }
        #pragma unroll
        for (int d = 0; d < 8; d++) sA[l * SA_STRIDE + qo + d] = o[d] * inv;
    }
    __syncthreads();

    {
        const int l  = tid % 36;
        const int j0 = tid / 36;
        const float* orow = sA + l * SA_STRIDE;
        for (int k = 0; k < 8; k++) {
            int j = j0 + 8 * k;
            float acc = b_out[j];
            const float* wr = w_out + j * 64;
            #pragma unroll
            for (int i = 0; i < 64; i++) acc = fmaf(orow[i], wr[i], acc);
            sQ[l * SK_STRIDE + j] = acc;
        }
    }
    __syncthreads();

    if (tid < 256) {
        int w = tid >> 6, i = tid & 63;
        float s = 0.f;
        #pragma unroll
        for (int p = 0; p < 9; p++) s += sQ[(w * 9 + p) * SK_STRIDE + i];
        pooled[w][i] = s * (1.f / 9.f);
    }
    __syncthreads();
    if (tid < 16) {
        int w = tid >> 2, r = tid & 3;
        float acc = se_b1[w * 4 + r];
        #pragma unroll
        for (int i = 0; i < 64; i++)
            acc = fmaf(pooled[w][i], se_w1[(w * 4 + r) * 64 + i], acc);
        hr[w][r] = fmaxf(acc, 0.f);
    }
    __syncthreads();
    if (tid < 256) {
        int w = tid >> 6, i = tid & 63;   // i = ic
        float acc = se_b2[w * 64 + i];
        #pragma unroll
        for (int r = 0; r < 4; r++)
            acc = fmaf(hr[w][r], se_w2[(w * 64 + i) * 4 + r], acc);
        float g = 1.f / (1.f + expf(-acc));
        #pragma unroll
        for (int p = 0; p < 9; p++) {
            float v = sQ[(w * 9 + p) * SK_STRIDE + i] * g;
            __nv_bfloat16 hi = __float2bfloat16(v);
            __nv_bfloat16 lo = __float2bfloat16(v - __bfloat162float(hi));
            int idx = ((w * 9 + p) * 64 + i) * WROW + b;
            g_Whi[idx] = hi;
            g_Wlo[idx] = lo;
        }
    }
}

// ===========================================================================
// Stage 2: WMMA bf16-split implicit-GEMM conv + LN + residual.
// CTA = one 16x16 px tile, 256 threads, 2 CTAs/SM.
// A double-buffered via cp.async (overlaps mainloop); W single-buffered.
// A buf: [18*18 pos][24] hi then lo (15552 bf16 each, x2 buffers)
// W:     [9 taps][16 ic][72 oc] hi then lo
// ===========================================================================
#define ALDA   24
#define A_ELEMS (18 * 18 * ALDA)                 // 7776 bf16
#define ABUF_E  (2 * A_ELEMS)                    // hi+lo per buffer
#define W_ELEMS (9 * 16 * WROW)                  // 10368 bf16
#define WHI_E  (2 * ABUF_E)
#define WLO_E  (2 * ABUF_E + W_ELEMS)
#define SMEM2_BYTES ((2 * ABUF_E + 2 * W_ELEMS) * 2)   // 103680 B
#define DSTRIDE 68

typedef wmma::fragment<wmma::matrix_a, 16, 16, 16, __nv_bfloat16, wmma::row_major> FragA;
typedef wmma::fragment<wmma::matrix_b, 16, 16, 16, __nv_bfloat16, wmma::row_major> FragB;
typedef wmma::fragment<wmma::accumulator, 16, 16, 16, float> FragC;

__global__ __launch_bounds__(256, 2) void stage2_kernel(
    const float* __restrict__ x, const float* __restrict__ ln_w,
    const float* __restrict__ ln_b, float* __restrict__ out)
{
    extern __shared__ __nv_bfloat16 sb[];
    __nv_bfloat16* Whi = sb + WHI_E;
    __nv_bfloat16* Wlo = sb + WLO_E;

    const int blk  = blockIdx.x;
    const int tile = blk & 63;
    const int w    = (blk >> 6) & 3;
    const int b    = blk >> 8;
    const int ty0  = (tile >> 3) << 4;
    const int tx0  = (tile & 7) << 4;
    const int wh   = w >> 1, ww = w & 1;

    const int tid = threadIdx.x;
    const int wid = tid >> 5;

    FragC acc[2][4];
    #pragma unroll
    for (int r = 0; r < 2; r++)
        #pragma unroll
        for (int n = 0; n < 4; n++) wmma::fill_fragment(acc[r][n], 0.f);

    // ---- async A staging for one 16-ic chunk into buffer bp ----
    auto stageA = [&](int c, int bp) {
        const int ic0 = c * 16;
        __nv_bfloat16* Abase = sb + bp * ABUF_E;
        for (int t = tid; t < 1296; t += 256) {
            int quad = t & 1;
            int hl   = (t >> 1) & 1;
            int pos  = t >> 2;
            int hrow = pos / 18, hcol = pos - hrow * 18;
            int ly = ty0 + hrow - 1, lx = tx0 + hcol - 1;
            bool ok = (ly >= 0 && ly < 128 && lx >= 0 && lx < 128);
            int cy = ok ? ly : 0, cx = ok ? lx : 0;
            size_t go = ((size_t)(b * 256 + wh * 128 + cy) * 256
                         + ww * 128 + cx) * 64 + ic0 + quad * 8;
            const __nv_bfloat16* src = (hl ? g_xlo : g_xhi) + go;
            uint32_t dst = smem_u32(Abase + hl * A_ELEMS + pos * ALDA + quad * 8);
            cp16(dst, src, ok);
        }
    };
    auto stageW = [&](int c) {
        const int ic0 = c * 16;
        for (int t = tid; t < 1296; t += 256) {           // 9*16*9
            int tap = t / 144, rem = t - tap * 144;
            int row = rem / 9, q = rem - row * 9;
            size_t so = (size_t)((w * 9 + tap) * 64 + ic0 + row) * WROW + q * 8;
            int   dof = (tap * 16 + row) * WROW + q * 8;
            *(uint4*)(Whi + dof) = *(const uint4*)(g_Whi + so);
            *(uint4*)(Wlo + dof) = *(const uint4*)(g_Wlo + so);
        }
    };

    // ---- prologue: A(0) async + W(0) ----
    stageA(0, 0);
    CP_COMMIT();
    stageW(0);
    CP_WAIT0();
    __syncthreads();

    #pragma unroll 1
    for (int c = 0; c < 4; c++) {
        // prefetch next A chunk while this chunk's MMAs run
        if (c < 3) { stageA(c + 1, (c + 1) & 1); CP_COMMIT(); }

        const __nv_bfloat16* Ahi = sb + (c & 1) * ABUF_E;
        const __nv_bfloat16* Alo = Ahi + A_ELEMS;

        #pragma unroll 1
        for (int tap = 0; tap < 9; tap++) {
            const int dy = tap / 3, dx = tap - 3 * (tap / 3);
            FragB bh[4], bl[4];
            const __nv_bfloat16* wbh = Whi + tap * 16 * WROW;
            const __nv_bfloat16* wbl = Wlo + tap * 16 * WROW;
            #pragma unroll
            for (int n = 0; n < 4; n++) {
                wmma::load_matrix_sync(bh[n], wbh + n * 16, WROW);
                wmma::load_matrix_sync(bl[n], wbl + n * 16, WROW);
            }
            #pragma unroll
            for (int r = 0; r < 2; r++) {
                const int yrow = wid * 2 + r;
                const int aoff = ((yrow + dy) * 18 + dx) * ALDA;
                FragA ah, al;
                wmma::load_matrix_sync(ah, Ahi + aoff, ALDA);
                wmma::load_matrix_sync(al, Alo + aoff, ALDA);
                #pragma unroll
                for (int n = 0; n < 4; n++) {
                    wmma::mma_sync(acc[r][n], ah, bh[n], acc[r][n]);
                    wmma::mma_sync(acc[r][n], al, bh[n], acc[r][n]);
                    wmma::mma_sync(acc[r][n], ah, bl[n], acc[r][n]);
                }
            }
        }
        __syncthreads();              // all warps done with W(c); A(c) safe till c+2
        if (c < 3) {
            stageW(c + 1);
            CP_WAIT0();               // A(c+1) landed (overlapped with mainloop)
            __syncthreads();
        }
    }

    // ---- epilogue: dump to smem, LN over oc, residual, store ----
    float* D = (float*)sb;                           // [256 px][68]
    #pragma unroll
    for (int r = 0; r < 2; r++) {
        const int yrow = wid * 2 + r;
        #pragma unroll
        for (int n = 0; n < 4; n++)
            wmma::store_matrix_sync(D + (yrow * 16) * DSTRIDE + n * 16,
                                    acc[r][n], DSTRIDE, wmma::mem_row_major);
    }
    __syncthreads();

    {
        const int y  = tid >> 4, xq = tid & 15;
        const float* drow = D + tid * DSTRIDE;
        float s = 0.f, sq = 0.f;
        #pragma unroll
        for (int oc = 0; oc < 64; oc++) {
            float d = drow[oc];
            s += d;
            sq = fmaf(d, d, sq);
        }
        float mu   = s * (1.f / 64.f);
        float rstd = rsqrtf(sq * (1.f / 64.f) - mu * mu + 1e-5f);
        const int gy = wh * 128 + ty0 + y;
        const int gx = ww * 128 + tx0 + xq;
        #pragma unroll 4
        for (int oc = 0; oc < 64; oc++) {
            size_t gi = ((size_t)(b * 64 + oc) * 256 + gy) * 256 + gx;
            out[gi] = x[gi] + (drow[oc] - mu) * rstd * ln_w[oc] + ln_b[oc];
        }
    }
}

// ===========================================================================
extern "C" void kernel_launch(void* const* d_in, const int* in_sizes, int n_in,
                              void* d_out, int out_size)
{
    (void)in_sizes; (void)n_in; (void)out_size;
    const float* x      = (const float*)d_in[0];
    const float* conv_w = (const float*)d_in[1];
    const float* w_qkv  = (const float*)d_in[2];
    const float* b_qkv  = (const float*)d_in[3];
    const float* w_out  = (const float*)d_in[4];
    const float* b_out  = (const float*)d_in[5];
    const float* se_w1  = (const float*)d_in[6];
    const float* se_b1  = (const float*)d_in[7];
    const float* se_w2  = (const float*)d_in[8];
    const float* se_b2  = (const float*)d_in[9];
    const float* ln_w   = (const float*)d_in[10];
    const float* ln_b   = (const float*)d_in[11];
    float* out = (float*)d_out;

    cudaFuncSetAttribute(stage2_kernel,
                         cudaFuncAttributeMaxDynamicSharedMemorySize, SMEM2_BYTES);

    stage0_kernel<<<2048, 256>>>(x);
    stage1_kernel<<<64, 288>>>(conv_w, w_qkv, b_qkv, w_out, b_out,
                               se_w1, se_b1, se_w2, se_b2);
    stage2_kernel<<<2048, 256, SMEM2_BYTES>>>(x, ln_w, ln_b, out);
}

// round 12
// speedup vs baseline: 1.1651x; 1.1140x over previous
#include <cuda_runtime.h>
#include <cuda_bf16.h>
#include <mma.h>
#include <math.h>
#include <stdint.h>

using namespace nvcuda;

#define WINN 4
#define LTOK 36

// Dynamic conv weights, bf16 hi/lo, layout [w*9+p][ic(64)][oc stride 72]
#define WROW 72
__device__ __nv_bfloat16 g_Whi[36 * 64 * WROW];
__device__ __nv_bfloat16 g_Wlo[36 * 64 * WROW];

// Pre-converted input, channel-last bf16 hi/lo: [b][y][x][c=64]
__device__ __nv_bfloat16 g_xhi[8 * 256 * 256 * 64];
__device__ __nv_bfloat16 g_xlo[8 * 256 * 256 * 64];

__device__ __forceinline__ uint32_t smem_u32(const void* p) {
    uint32_t a;
    asm("{ .reg .u64 t; cvta.to.shared.u64 t, %1; cvt.u32.u64 %0, t; }" : "=r"(a) : "l"(p));
    return a;
}
__device__ __forceinline__ void cp16(uint32_t dst, const void* src, bool valid) {
    int sz = valid ? 16 : 0;
    asm volatile("cp.async.cg.shared.global [%0], [%1], 16, %2;\n"
                 :: "r"(dst), "l"(src), "r"(sz) : "memory");
}
#define CP_COMMIT() asm volatile("cp.async.commit_group;\n" ::: "memory")
#define CP_WAIT0()  asm volatile("cp.async.wait_group 0;\n" ::: "memory")

// ===========================================================================
// Fused stage 0+1.
// Blocks 0..63   : stage1 (dynamic conv-kernel construction), one block per oc.
// Blocks 64..2111: stage0 (x fp32 -> channel-last bf16 hi/lo), one block per
//                  (b, y) row, smem-transposed for coalesced writes.
// ===========================================================================
#define SQ_STRIDE 193
#define SA_STRIDE 65
#define SK_STRIDE 65
#define S0_ROW 72                      // bf16 per px row in smem (144B, padded)
#define SMEM01_BYTES (2 * 256 * S0_ROW * 2)   // 73728 B

__global__ __launch_bounds__(288) void stage01_kernel(
    const float* __restrict__ x,
    const float* __restrict__ conv_w, const float* __restrict__ w_qkv,
    const float* __restrict__ b_qkv,  const float* __restrict__ w_out,
    const float* __restrict__ b_out,  const float* __restrict__ se_w1,
    const float* __restrict__ se_b1,  const float* __restrict__ se_w2,
    const float* __restrict__ se_b2)
{
    extern __shared__ char smraw[];
    const int tid = threadIdx.x;

    if (blockIdx.x >= 64) {
        // ================= stage 0 =================
        __nv_bfloat16* shi = (__nv_bfloat16*)smraw;            // [256][72]
        __nv_bfloat16* slo = shi + 256 * S0_ROW;

        const int bid = blockIdx.x - 64;
        const int y   = bid & 255;
        const int b   = bid >> 8;

        if (tid < 256) {
            const int xq = tid;
            const float* src = x + (size_t)b * (64 * 65536) + y * 256 + xq;
            #pragma unroll
            for (int g = 0; g < 8; g++) {
                __nv_bfloat16 hi[8], lo[8];
                #pragma unroll
                for (int c = 0; c < 8; c++) {
                    float v = src[(size_t)(g * 8 + c) * 65536];
                    __nv_bfloat16 h = __float2bfloat16(v);
                    hi[c] = h;
                    lo[c] = __float2bfloat16(v - __bfloat162float(h));
                }
                *(uint4*)(shi + xq * S0_ROW + g * 8) = *(const uint4*)hi;
                *(uint4*)(slo + xq * S0_ROW + g * 8) = *(const uint4*)lo;
            }
        }
        __syncthreads();
        // coalesced write-out: 2048 uint4 per buffer
        if (tid < 256) {
            const size_t rowo = ((size_t)(b * 256 + y) * 256) * 64;
            #pragma unroll
            for (int it = 0; it < 8; it++) {
                int i   = tid + it * 256;
                int px  = i >> 3, quad = i & 7;
                *(uint4*)(g_xhi + rowo + (size_t)i * 8) =          // px*64 + quad*8
                    *(const uint4*)(shi + px * S0_ROW + quad * 8);
                *(uint4*)(g_xlo + rowo + (size_t)i * 8) =
                    *(const uint4*)(slo + px * S0_ROW + quad * 8);
            }
        }
        return;
    }

    // ================= stage 1 =================
    float* sA = (float*)smraw;                       // [36][65]
    float* sQ = sA + LTOK * SA_STRIDE;               // [36][193] / kern2 [36][65]
    float* pooled = sQ + LTOK * SQ_STRIDE;           // [4][64]
    float* hr     = pooled + 256;                    // [4][4]

    const int b = blockIdx.x;

    for (int t = tid; t < LTOK * 64; t += 288) {
        int l = t >> 6, i = t & 63;
        int w = l / 9, p = l - w * 9;
        sA[l * SA_STRIDE + i] = conv_w[(((w * 64 + b) * 64 + i) * 9) + p];
    }
    __syncthreads();

    {
        const int l  = tid % 36;
        const int j0 = tid / 36;
        const float* kr = sA + l * SA_STRIDE;
        for (int k = 0; k < 24; k++) {
            int j = j0 + 8 * k;
            float acc = b_qkv[j];
            const float* wr = w_qkv + j * 64;
            #pragma unroll
            for (int i = 0; i < 64; i++) acc = fmaf(kr[i], wr[i], acc);
            sQ[l * SQ_STRIDE + j] = acc;
        }
    }
    __syncthreads();

    {
        int h = tid / 36, l = tid - h * 36;
        const int qo = h * 8;
        const float scale = 0.35355339059327373f;
        float qv[8];
        #pragma unroll
        for (int d = 0; d < 8; d++) qv[d] = sQ[l * SQ_STRIDE + qo + d] * scale;

        float sc[36];
        float mx = -1e30f;
        for (int m = 0; m < 36; m++) {
            float s = 0.f;
            #pragma unroll
            for (int d = 0; d < 8; d++)
                s = fmaf(qv[d], sQ[m * SQ_STRIDE + 64 + qo + d], s);
            sc[m] = s;
            mx = fmaxf(mx, s);
        }
        float sum = 0.f;
        for (int m = 0; m < 36; m++) { float e = expf(sc[m] - mx); sc[m] = e; sum += e; }
        float inv = 1.f / sum;
        float o[8];
        #pragma unroll
        for (int d = 0; d < 8; d++) o[d] = 0.f;
        for (int m = 0; m < 36; m++) {
            float a = sc[m];
            #pragma unroll
            for (int d = 0; d < 8; d++)
                o[d] = fmaf(a, sQ[m * SQ_STRIDE + 128 + qo + d], o[d]);
        }
        #pragma unroll
        for (int d = 0; d < 8; d++) sA[l * SA_STRIDE + qo + d] = o[d] * inv;
    }
    __syncthreads();

    {
        const int l  = tid % 36;
        const int j0 = tid / 36;
        const float* orow = sA + l * SA_STRIDE;
        for (int k = 0; k < 8; k++) {
            int j = j0 + 8 * k;
            float acc = b_out[j];
            const float* wr = w_out + j * 64;
            #pragma unroll
            for (int i = 0; i < 64; i++) acc = fmaf(orow[i], wr[i], acc);
            sQ[l * SK_STRIDE + j] = acc;
        }
    }
    __syncthreads();

    if (tid < 256) {
        int w = tid >> 6, i = tid & 63;
        float s = 0.f;
        #pragma unroll
        for (int p = 0; p < 9; p++) s += sQ[(w * 9 + p) * SK_STRIDE + i];
        pooled[w * 64 + i] = s * (1.f / 9.f);
    }
    __syncthreads();
    if (tid < 16) {
        int w = tid >> 2, r = tid & 3;
        float acc = se_b1[w * 4 + r];
        #pragma unroll
        for (int i = 0; i < 64; i++)
            acc = fmaf(pooled[w * 64 + i], se_w1[(w * 4 + r) * 64 + i], acc);
        hr[w * 4 + r] = fmaxf(acc, 0.f);
    }
    __syncthreads();
    if (tid < 256) {
        int w = tid >> 6, i = tid & 63;   // i = ic
        float acc = se_b2[w * 64 + i];
        #pragma unroll
        for (int r = 0; r < 4; r++)
            acc = fmaf(hr[w * 4 + r], se_w2[(w * 64 + i) * 4 + r], acc);
        float g = 1.f / (1.f + expf(-acc));
        #pragma unroll
        for (int p = 0; p < 9; p++) {
            float v = sQ[(w * 9 + p) * SK_STRIDE + i] * g;
            __nv_bfloat16 hi = __float2bfloat16(v);
            __nv_bfloat16 lo = __float2bfloat16(v - __bfloat162float(hi));
            int idx = ((w * 9 + p) * 64 + i) * WROW + b;
            g_Whi[idx] = hi;
            g_Wlo[idx] = lo;
        }
    }
}

// ===========================================================================
// Stage 2: WMMA bf16-split implicit-GEMM conv + LN + residual.
// CTA = one 16x16 px tile, 256 threads, 2 CTAs/SM.
// A double-buffered via cp.async; mma order pass-outer for accumulator ILP.
// ===========================================================================
#define ALDA   24
#define A_ELEMS (18 * 18 * ALDA)                 // 7776 bf16
#define ABUF_E  (2 * A_ELEMS)                    // hi+lo per buffer
#define W_ELEMS (9 * 16 * WROW)                  // 10368 bf16
#define WHI_E  (2 * ABUF_E)
#define WLO_E  (2 * ABUF_E + W_ELEMS)
#define SMEM2_BYTES ((2 * ABUF_E + 2 * W_ELEMS) * 2)   // 103680 B
#define DSTRIDE 68

typedef wmma::fragment<wmma::matrix_a, 16, 16, 16, __nv_bfloat16, wmma::row_major> FragA;
typedef wmma::fragment<wmma::matrix_b, 16, 16, 16, __nv_bfloat16, wmma::row_major> FragB;
typedef wmma::fragment<wmma::accumulator, 16, 16, 16, float> FragC;

__global__ __launch_bounds__(256, 2) void stage2_kernel(
    const float* __restrict__ x, const float* __restrict__ ln_w,
    const float* __restrict__ ln_b, float* __restrict__ out)
{
    extern __shared__ __nv_bfloat16 sb[];
    __nv_bfloat16* Whi = sb + WHI_E;
    __nv_bfloat16* Wlo = sb + WLO_E;

    const int blk  = blockIdx.x;
    const int tile = blk & 63;
    const int w    = (blk >> 6) & 3;
    const int b    = blk >> 8;
    const int ty0  = (tile >> 3) << 4;
    const int tx0  = (tile & 7) << 4;
    const int wh   = w >> 1, ww = w & 1;

    const int tid = threadIdx.x;
    const int wid = tid >> 5;

    FragC acc[2][4];
    #pragma unroll
    for (int r = 0; r < 2; r++)
        #pragma unroll
        for (int n = 0; n < 4; n++) wmma::fill_fragment(acc[r][n], 0.f);

    auto stageA = [&](int c, int bp) {
        const int ic0 = c * 16;
        __nv_bfloat16* Abase = sb + bp * ABUF_E;
        for (int t = tid; t < 1296; t += 256) {
            int quad = t & 1;
            int hl   = (t >> 1) & 1;
            int pos  = t >> 2;
            int hrow = pos / 18, hcol = pos - hrow * 18;
            int ly = ty0 + hrow - 1, lx = tx0 + hcol - 1;
            bool ok = (ly >= 0 && ly < 128 && lx >= 0 && lx < 128);
            int cy = ok ? ly : 0, cx = ok ? lx : 0;
            size_t go = ((size_t)(b * 256 + wh * 128 + cy) * 256
                         + ww * 128 + cx) * 64 + ic0 + quad * 8;
            const __nv_bfloat16* src = (hl ? g_xlo : g_xhi) + go;
            uint32_t dst = smem_u32(Abase + hl * A_ELEMS + pos * ALDA + quad * 8);
            cp16(dst, src, ok);
        }
    };
    auto stageW = [&](int c) {
        const int ic0 = c * 16;
        for (int t = tid; t < 1296; t += 256) {           // 9*16*9
            int tap = t / 144, rem = t - tap * 144;
            int row = rem / 9, q = rem - row * 9;
            size_t so = (size_t)((w * 9 + tap) * 64 + ic0 + row) * WROW + q * 8;
            int   dof = (tap * 16 + row) * WROW + q * 8;
            *(uint4*)(Whi + dof) = *(const uint4*)(g_Whi + so);
            *(uint4*)(Wlo + dof) = *(const uint4*)(g_Wlo + so);
        }
    };

    // prologue
    stageA(0, 0);
    CP_COMMIT();
    stageW(0);
    CP_WAIT0();
    __syncthreads();

    #pragma unroll 1
    for (int c = 0; c < 4; c++) {
        if (c < 3) { stageA(c + 1, (c + 1) & 1); CP_COMMIT(); }

        const __nv_bfloat16* Ahi = sb + (c & 1) * ABUF_E;
        const __nv_bfloat16* Alo = Ahi + A_ELEMS;

        #pragma unroll 1
        for (int tap = 0; tap < 9; tap++) {
            const int dy = tap / 3, dx = tap - 3 * (tap / 3);
            FragB bh[4], bl[4];
            FragA ah[2], al[2];
            const __nv_bfloat16* wbh = Whi + tap * 16 * WROW;
            const __nv_bfloat16* wbl = Wlo + tap * 16 * WROW;
            #pragma unroll
            for (int n = 0; n < 4; n++) {
                wmma::load_matrix_sync(bh[n], wbh + n * 16, WROW);
                wmma::load_matrix_sync(bl[n], wbl + n * 16, WROW);
            }
            #pragma unroll
            for (int r = 0; r < 2; r++) {
                const int aoff = ((wid * 2 + r + dy) * 18 + dx) * ALDA;
                wmma::load_matrix_sync(ah[r], Ahi + aoff, ALDA);
                wmma::load_matrix_sync(al[r], Alo + aoff, ALDA);
            }
            // pass-outer order: dependent reuse of each acc is 8 mmas apart
            #pragma unroll
            for (int r = 0; r < 2; r++)
                #pragma unroll
                for (int n = 0; n < 4; n++)
                    wmma::mma_sync(acc[r][n], ah[r], bh[n], acc[r][n]);
            #pragma unroll
            for (int r = 0; r < 2; r++)
                #pragma unroll
                for (int n = 0; n < 4; n++)
                    wmma::mma_sync(acc[r][n], al[r], bh[n], acc[r][n]);
            #pragma unroll
            for (int r = 0; r < 2; r++)
                #pragma unroll
                for (int n = 0; n < 4; n++)
                    wmma::mma_sync(acc[r][n], ah[r], bl[n], acc[r][n]);
        }
        __syncthreads();
        if (c < 3) {
            stageW(c + 1);
            CP_WAIT0();
            __syncthreads();
        }
    }

    // ---- epilogue: dump to smem, LN over oc, residual, store ----
    float* D = (float*)sb;                           // [256 px][68]
    #pragma unroll
    for (int r = 0; r < 2; r++) {
        const int yrow = wid * 2 + r;
        #pragma unroll
        for (int n = 0; n < 4; n++)
            wmma::store_matrix_sync(D + (yrow * 16) * DSTRIDE + n * 16,
                                    acc[r][n], DSTRIDE, wmma::mem_row_major);
    }
    __syncthreads();

    {
        const int y  = tid >> 4, xq = tid & 15;
        const float* drow = D + tid * DSTRIDE;
        float s = 0.f, sq = 0.f;
        #pragma unroll
        for (int oc = 0; oc < 64; oc++) {
            float d = drow[oc];
            s += d;
            sq = fmaf(d, d, sq);
        }
        float mu   = s * (1.f / 64.f);
        float rstd = rsqrtf(sq * (1.f / 64.f) - mu * mu + 1e-5f);
        const int gy = wh * 128 + ty0 + y;
        const int gx = ww * 128 + tx0 + xq;
        #pragma unroll 4
        for (int oc = 0; oc < 64; oc++) {
            size_t gi = ((size_t)(b * 64 + oc) * 256 + gy) * 256 + gx;
            out[gi] = x[gi] + (drow[oc] - mu) * rstd * ln_w[oc] + ln_b[oc];
        }
    }
}

// ===========================================================================
extern "C" void kernel_launch(void* const* d_in, const int* in_sizes, int n_in,
                              void* d_out, int out_size)
{
    (void)in_sizes; (void)n_in; (void)out_size;
    const float* x      = (const float*)d_in[0];
    const float* conv_w = (const float*)d_in[1];
    const float* w_qkv  = (const float*)d_in[2];
    const float* b_qkv  = (const float*)d_in[3];
    const float* w_out  = (const float*)d_in[4];
    const float* b_out  = (const float*)d_in[5];
    const float* se_w1  = (const float*)d_in[6];
    const float* se_b1  = (const float*)d_in[7];
    const float* se_w2  = (const float*)d_in[8];
    const float* se_b2  = (const float*)d_in[9];
    const float* ln_w   = (const float*)d_in[10];
    const float* ln_b   = (const float*)d_in[11];
    float* out = (float*)d_out;

    cudaFuncSetAttribute(stage01_kernel,
                         cudaFuncAttributeMaxDynamicSharedMemorySize, SMEM01_BYTES);
    cudaFuncSetAttribute(stage2_kernel,
                         cudaFuncAttributeMaxDynamicSharedMemorySize, SMEM2_BYTES);

    stage01_kernel<<<2112, 288, SMEM01_BYTES>>>(x, conv_w, w_qkv, b_qkv, w_out,
                                                b_out, se_w1, se_b1, se_w2, se_b2);
    stage2_kernel<<<2048, 256, SMEM2_BYTES>>>(x, ln_w, ln_b, out);
}

// round 13
// speedup vs baseline: 1.6368x; 1.4048x over previous
#include <cuda_runtime.h>
#include <cuda_fp16.h>
#include <mma.h>
#include <math.h>
#include <stdint.h>

using namespace nvcuda;

#define WINN 4
#define LTOK 36

// Dynamic conv weights, fp16 hi/lo, layout [w*9+p][ic(64)][oc stride 72]
#define WROW 72
__device__ __half g_Whi[36 * 64 * WROW];
__device__ __half g_Wlo[36 * 64 * WROW];

// Pre-converted input, channel-last fp16: [b][y][x][c=64]
__device__ __half g_xh[8 * 256 * 256 * 64];

__device__ __forceinline__ uint32_t smem_u32(const void* p) {
    uint32_t a;
    asm("{ .reg .u64 t; cvta.to.shared.u64 t, %1; cvt.u32.u64 %0, t; }" : "=r"(a) : "l"(p));
    return a;
}
__device__ __forceinline__ void cp16(uint32_t dst, const void* src, bool valid) {
    int sz = valid ? 16 : 0;
    asm volatile("cp.async.cg.shared.global [%0], [%1], 16, %2;\n"
                 :: "r"(dst), "l"(src), "r"(sz) : "memory");
}
#define CP_COMMIT() asm volatile("cp.async.commit_group;\n" ::: "memory")
#define CP_WAIT0()  asm volatile("cp.async.wait_group 0;\n" ::: "memory")

// ===========================================================================
// Fused stage 0+1.
// Blocks 0..63   : stage1 (dynamic conv-kernel construction), one block per oc.
// Blocks 64..2111: stage0 (x fp32 -> channel-last fp16), smem-transposed
//                  for coalesced writes.
// ===========================================================================
#define SQ_STRIDE 193
#define SA_STRIDE 65
#define SK_STRIDE 65
#define S0_ROW 72                      // fp16 per px row in smem (144B, padded)
#define SMEM01_BYTES (256 * S0_ROW * 2 < 46000 ? 46000 : 256 * S0_ROW * 2)

__global__ __launch_bounds__(288) void stage01_kernel(
    const float* __restrict__ x,
    const float* __restrict__ conv_w, const float* __restrict__ w_qkv,
    const float* __restrict__ b_qkv,  const float* __restrict__ w_out,
    const float* __restrict__ b_out,  const float* __restrict__ se_w1,
    const float* __restrict__ se_b1,  const float* __restrict__ se_w2,
    const float* __restrict__ se_b2)
{
    extern __shared__ char smraw[];
    const int tid = threadIdx.x;

    if (blockIdx.x >= 64) {
        // ================= stage 0 =================
        __half* sh = (__half*)smraw;                 // [256][72]

        const int bid = blockIdx.x - 64;
        const int y   = bid & 255;
        const int b   = bid >> 8;

        if (tid < 256) {
            const int xq = tid;
            const float* src = x + (size_t)b * (64 * 65536) + y * 256 + xq;
            #pragma unroll
            for (int g = 0; g < 8; g++) {
                __half h[8];
                #pragma unroll
                for (int c = 0; c < 8; c++)
                    h[c] = __float2half(src[(size_t)(g * 8 + c) * 65536]);
                *(uint4*)(sh + xq * S0_ROW + g * 8) = *(const uint4*)h;
            }
        }
        __syncthreads();
        // coalesced write-out: 2048 uint4
        if (tid < 256) {
            const size_t rowo = ((size_t)(b * 256 + y) * 256) * 64;
            #pragma unroll
            for (int it = 0; it < 8; it++) {
                int i  = tid + it * 256;
                int px = i >> 3, quad = i & 7;
                *(uint4*)(g_xh + rowo + (size_t)i * 8) =
                    *(const uint4*)(sh + px * S0_ROW + quad * 8);
            }
        }
        return;
    }

    // ================= stage 1 =================
    float* sA = (float*)smraw;                       // [36][65]
    float* sQ = sA + LTOK * SA_STRIDE;               // [36][193] / kern2 [36][65]
    float* pooled = sQ + LTOK * SQ_STRIDE;           // [4][64]
    float* hr     = pooled + 256;                    // [4][4]

    const int b = blockIdx.x;

    for (int t = tid; t < LTOK * 64; t += 288) {
        int l = t >> 6, i = t & 63;
        int w = l / 9, p = l - w * 9;
        sA[l * SA_STRIDE + i] = conv_w[(((w * 64 + b) * 64 + i) * 9) + p];
    }
    __syncthreads();

    {
        const int l  = tid % 36;
        const int j0 = tid / 36;
        const float* kr = sA + l * SA_STRIDE;
        for (int k = 0; k < 24; k++) {
            int j = j0 + 8 * k;
            float acc = b_qkv[j];
            const float* wr = w_qkv + j * 64;
            #pragma unroll
            for (int i = 0; i < 64; i++) acc = fmaf(kr[i], wr[i], acc);
            sQ[l * SQ_STRIDE + j] = acc;
        }
    }
    __syncthreads();

    {
        int h = tid / 36, l = tid - h * 36;
        const int qo = h * 8;
        const float scale = 0.35355339059327373f;
        float qv[8];
        #pragma unroll
        for (int d = 0; d < 8; d++) qv[d] = sQ[l * SQ_STRIDE + qo + d] * scale;

        float sc[36];
        float mx = -1e30f;
        for (int m = 0; m < 36; m++) {
            float s = 0.f;
            #pragma unroll
            for (int d = 0; d < 8; d++)
                s = fmaf(qv[d], sQ[m * SQ_STRIDE + 64 + qo + d], s);
            sc[m] = s;
            mx = fmaxf(mx, s);
        }
        float sum = 0.f;
        for (int m = 0; m < 36; m++) { float e = expf(sc[m] - mx); sc[m] = e; sum += e; }
        float inv = 1.f / sum;
        float o[8];
        #pragma unroll
        for (int d = 0; d < 8; d++) o[d] = 0.f;
        for (int m = 0; m < 36; m++) {
            float a = sc[m];
            #pragma unroll
            for (int d = 0; d < 8; d++)
                o[d] = fmaf(a, sQ[m * SQ_STRIDE + 128 + qo + d], o[d]);
        }
        #pragma unroll
        for (int d = 0; d < 8; d++) sA[l * SA_STRIDE + qo + d] = o[d] * inv;
    }
    __syncthreads();

    {
        const int l  = tid % 36;
        const int j0 = tid / 36;
        const float* orow = sA + l * SA_STRIDE;
        for (int k = 0; k < 8; k++) {
            int j = j0 + 8 * k;
            float acc = b_out[j];
            const float* wr = w_out + j * 64;
            #pragma unroll
            for (int i = 0; i < 64; i++) acc = fmaf(orow[i], wr[i], acc);
            sQ[l * SK_STRIDE + j] = acc;
        }
    }
    __syncthreads();

    if (tid < 256) {
        int w = tid >> 6, i = tid & 63;
        float s = 0.f;
        #pragma unroll
        for (int p = 0; p < 9; p++) s += sQ[(w * 9 + p) * SK_STRIDE + i];
        pooled[w * 64 + i] = s * (1.f / 9.f);
    }
    __syncthreads();
    if (tid < 16) {
        int w = tid >> 2, r = tid & 3;
        float acc = se_b1[w * 4 + r];
        #pragma unroll
        for (int i = 0; i < 64; i++)
            acc = fmaf(pooled[w * 64 + i], se_w1[(w * 4 + r) * 64 + i], acc);
        hr[w * 4 + r] = fmaxf(acc, 0.f);
    }
    __syncthreads();
    if (tid < 256) {
        int w = tid >> 6, i = tid & 63;   // i = ic
        float acc = se_b2[w * 64 + i];
        #pragma unroll
        for (int r = 0; r < 4; r++)
            acc = fmaf(hr[w * 4 + r], se_w2[(w * 64 + i) * 4 + r], acc);
        float g = 1.f / (1.f + expf(-acc));
        #pragma unroll
        for (int p = 0; p < 9; p++) {
            float v = sQ[(w * 9 + p) * SK_STRIDE + i] * g;
            __half hi = __float2half(v);
            __half lo = __float2half(v - __half2float(hi));
            int idx = ((w * 9 + p) * 64 + i) * WROW + b;
            g_Whi[idx] = hi;
            g_Wlo[idx] = lo;
        }
    }
}

// ===========================================================================
// Stage 2: fp16 2-pass WMMA implicit-GEMM conv + LN + residual.
// D = A_fp16 * (W_hi + W_lo).  CTA = 16x16 px tile, 256 threads, 2 CTAs/SM.
// A single-precision fp16, double-buffered via cp.async.
// A buf: [18*18 pos][24] (16 ic + 8 pad), lda = 24 (48B)
// W:     [9 taps][16 ic][72 oc] hi then lo, ldb = 72 (144B)
// ===========================================================================
#define ALDA   24
#define A_ELEMS (18 * 18 * ALDA)                 // 7776 fp16
#define W_ELEMS (9 * 16 * WROW)                  // 10368 fp16
#define WHI_E  (2 * A_ELEMS)
#define WLO_E  (2 * A_ELEMS + W_ELEMS)
#define SMEM2_BYTES ((2 * A_ELEMS + 2 * W_ELEMS) * 2)   // 72576 B
#define DSTRIDE 68

typedef wmma::fragment<wmma::matrix_a, 16, 16, 16, __half, wmma::row_major> FragA;
typedef wmma::fragment<wmma::matrix_b, 16, 16, 16, __half, wmma::row_major> FragB;
typedef wmma::fragment<wmma::accumulator, 16, 16, 16, float> FragC;

__global__ __launch_bounds__(256, 2) void stage2_kernel(
    const float* __restrict__ x, const float* __restrict__ ln_w,
    const float* __restrict__ ln_b, float* __restrict__ out)
{
    extern __shared__ __half sb[];
    __half* Whi = sb + WHI_E;
    __half* Wlo = sb + WLO_E;

    const int blk  = blockIdx.x;
    const int tile = blk & 63;
    const int w    = (blk >> 6) & 3;
    const int b    = blk >> 8;
    const int ty0  = (tile >> 3) << 4;
    const int tx0  = (tile & 7) << 4;
    const int wh   = w >> 1, ww = w & 1;

    const int tid = threadIdx.x;
    const int wid = tid >> 5;

    FragC acc[2][4];
    #pragma unroll
    for (int r = 0; r < 2; r++)
        #pragma unroll
        for (int n = 0; n < 4; n++) wmma::fill_fragment(acc[r][n], 0.f);

    auto stageA = [&](int c, int bp) {
        const int ic0 = c * 16;
        __half* Abase = sb + bp * A_ELEMS;
        for (int t = tid; t < 648; t += 256) {
            int quad = t & 1;
            int pos  = t >> 1;
            int hrow = pos / 18, hcol = pos - hrow * 18;
            int ly = ty0 + hrow - 1, lx = tx0 + hcol - 1;
            bool ok = (ly >= 0 && ly < 128 && lx >= 0 && lx < 128);
            int cy = ok ? ly : 0, cx = ok ? lx : 0;
            size_t go = ((size_t)(b * 256 + wh * 128 + cy) * 256
                         + ww * 128 + cx) * 64 + ic0 + quad * 8;
            uint32_t dst = smem_u32(Abase + pos * ALDA + quad * 8);
            cp16(dst, g_xh + go, ok);
        }
    };
    auto stageW = [&](int c) {
        const int ic0 = c * 16;
        for (int t = tid; t < 1296; t += 256) {           // 9*16*9
            int tap = t / 144, rem = t - tap * 144;
            int row = rem / 9, q = rem - row * 9;
            size_t so = (size_t)((w * 9 + tap) * 64 + ic0 + row) * WROW + q * 8;
            int   dof = (tap * 16 + row) * WROW + q * 8;
            *(uint4*)(Whi + dof) = *(const uint4*)(g_Whi + so);
            *(uint4*)(Wlo + dof) = *(const uint4*)(g_Wlo + so);
        }
    };

    // prologue
    stageA(0, 0);
    CP_COMMIT();
    stageW(0);
    CP_WAIT0();
    __syncthreads();

    #pragma unroll 1
    for (int c = 0; c < 4; c++) {
        if (c < 3) { stageA(c + 1, (c + 1) & 1); CP_COMMIT(); }

        const __half* Ab = sb + (c & 1) * A_ELEMS;

        #pragma unroll 1
        for (int tap = 0; tap < 9; tap++) {
            const int dy = tap / 3, dx = tap - 3 * (tap / 3);
            FragB bh[4], bl[4];
            FragA af[2];
            const __half* wbh = Whi + tap * 16 * WROW;
            const __half* wbl = Wlo + tap * 16 * WROW;
            #pragma unroll
            for (int n = 0; n < 4; n++) {
                wmma::load_matrix_sync(bh[n], wbh + n * 16, WROW);
                wmma::load_matrix_sync(bl[n], wbl + n * 16, WROW);
            }
            #pragma unroll
            for (int r = 0; r < 2; r++) {
                const int aoff = ((wid * 2 + r + dy) * 18 + dx) * ALDA;
                wmma::load_matrix_sync(af[r], Ab + aoff, ALDA);
            }
            // pass-outer: each acc reused 8 mmas apart
            #pragma unroll
            for (int r = 0; r < 2; r++)
                #pragma unroll
                for (int n = 0; n < 4; n++)
                    wmma::mma_sync(acc[r][n], af[r], bh[n], acc[r][n]);
            #pragma unroll
            for (int r = 0; r < 2; r++)
                #pragma unroll
                for (int n = 0; n < 4; n++)
                    wmma::mma_sync(acc[r][n], af[r], bl[n], acc[r][n]);
        }
        __syncthreads();
        if (c < 3) {
            stageW(c + 1);
            CP_WAIT0();
            __syncthreads();
        }
    }

    // ---- epilogue: dump to smem, LN over oc, residual, store ----
    float* D = (float*)sb;                           // [256 px][68]
    #pragma unroll
    for (int r = 0; r < 2; r++) {
        const int yrow = wid * 2 + r;
        #pragma unroll
        for (int n = 0; n < 4; n++)
            wmma::store_matrix_sync(D + (yrow * 16) * DSTRIDE + n * 16,
                                    acc[r][n], DSTRIDE, wmma::mem_row_major);
    }
    __syncthreads();

    {
        const int y  = tid >> 4, xq = tid & 15;
        const float* drow = D + tid * DSTRIDE;
        float s = 0.f, sq = 0.f;
        #pragma unroll
        for (int oc = 0; oc < 64; oc++) {
            float d = drow[oc];
            s += d;
            sq = fmaf(d, d, sq);
        }
        float mu   = s * (1.f / 64.f);
        float rstd = rsqrtf(sq * (1.f / 64.f) - mu * mu + 1e-5f);
        const int gy = wh * 128 + ty0 + y;
        const int gx = ww * 128 + tx0 + xq;
        #pragma unroll 4
        for (int oc = 0; oc < 64; oc++) {
            size_t gi = ((size_t)(b * 64 + oc) * 256 + gy) * 256 + gx;
            out[gi] = x[gi] + (drow[oc] - mu) * rstd * ln_w[oc] + ln_b[oc];
        }
    }
}

// ===========================================================================
extern "C" void kernel_launch(void* const* d_in, const int* in_sizes, int n_in,
                              void* d_out, int out_size)
{
    (void)in_sizes; (void)n_in; (void)out_size;
    const float* x      = (const float*)d_in[0];
    const float* conv_w = (const float*)d_in[1];
    const float* w_qkv  = (const float*)d_in[2];
    const float* b_qkv  = (const float*)d_in[3];
    const float* w_out  = (const float*)d_in[4];
    const float* b_out  = (const float*)d_in[5];
    const float* se_w1  = (const float*)d_in[6];
    const float* se_b1  = (const float*)d_in[7];
    const float* se_w2  = (const float*)d_in[8];
    const float* se_b2  = (const float*)d_in[9];
    const float* ln_w   = (const float*)d_in[10];
    const float* ln_b   = (const float*)d_in[11];
    float* out = (float*)d_out;

    cudaFuncSetAttribute(stage01_kernel,
                         cudaFuncAttributeMaxDynamicSharedMemorySize, SMEM01_BYTES);
    cudaFuncSetAttribute(stage2_kernel,
                         cudaFuncAttributeMaxDynamicSharedMemorySize, SMEM2_BYTES);

    stage01_kernel<<<2112, 288, SMEM01_BYTES>>>(x, conv_w, w_qkv, b_qkv, w_out,
                                                b_out, se_w1, se_b1, se_w2, se_b2);
    stage2_kernel<<<2048, 256, SMEM2_BYTES>>>(x, ln_w, ln_b, out);
}

// round 14
// speedup vs baseline: 1.7928x; 1.0953x over previous
#include <cuda_runtime.h>
#include <cuda_fp16.h>
#include <mma.h>
#include <math.h>
#include <stdint.h>

using namespace nvcuda;

#define WINN 4
#define LTOK 36

// Dynamic conv weights, fp16 hi/lo, layout [w*9+p][ic(64)][oc stride 72]
#define WROW 72
__device__ __half g_Whi[36 * 64 * WROW];
__device__ __half g_Wlo[36 * 64 * WROW];

__device__ __forceinline__ uint32_t smem_u32(const void* p) {
    uint32_t a;
    asm("{ .reg .u64 t; cvta.to.shared.u64 t, %1; cvt.u32.u64 %0, t; }" : "=r"(a) : "l"(p));
    return a;
}
__device__ __forceinline__ void cp16(uint32_t dst, const void* src) {
    asm volatile("cp.async.cg.shared.global [%0], [%1], 16;\n"
                 :: "r"(dst), "l"(src) : "memory");
}
#define CP_COMMIT() asm volatile("cp.async.commit_group;\n" ::: "memory")
#define CP_WAIT0()  asm volatile("cp.async.wait_group 0;\n" ::: "memory")

// ===========================================================================
// Stage 1: build dynamic conv kernels (one block per oc b = blockIdx.x).
// ===========================================================================
#define SQ_STRIDE 193
#define SA_STRIDE 65
#define SK_STRIDE 65

__global__ __launch_bounds__(288) void stage1_kernel(
    const float* __restrict__ conv_w, const float* __restrict__ w_qkv,
    const float* __restrict__ b_qkv,  const float* __restrict__ w_out,
    const float* __restrict__ b_out,  const float* __restrict__ se_w1,
    const float* __restrict__ se_b1,  const float* __restrict__ se_w2,
    const float* __restrict__ se_b2)
{
    const int b   = blockIdx.x;
    const int tid = threadIdx.x;

    __shared__ float sA[LTOK * SA_STRIDE];
    __shared__ float sQ[LTOK * SQ_STRIDE];
    __shared__ float pooled[4][64];
    __shared__ float hr[4][4];

    for (int t = tid; t < LTOK * 64; t += 288) {
        int l = t >> 6, i = t & 63;
        int w = l / 9, p = l - w * 9;
        sA[l * SA_STRIDE + i] = conv_w[(((w * 64 + b) * 64 + i) * 9) + p];
    }
    __syncthreads();

    {
        const int l  = tid % 36;
        const int j0 = tid / 36;
        const float* kr = sA + l * SA_STRIDE;
        for (int k = 0; k < 24; k++) {
            int j = j0 + 8 * k;
            float acc = b_qkv[j];
            const float* wr = w_qkv + j * 64;
            #pragma unroll
            for (int i = 0; i < 64; i++) acc = fmaf(kr[i], wr[i], acc);
            sQ[l * SQ_STRIDE + j] = acc;
        }
    }
    __syncthreads();

    {
        int h = tid / 36, l = tid - h * 36;
        const int qo = h * 8;
        const float scale = 0.35355339059327373f;
        float qv[8];
        #pragma unroll
        for (int d = 0; d < 8; d++) qv[d] = sQ[l * SQ_STRIDE + qo + d] * scale;

        float sc[36];
        float mx = -1e30f;
        for (int m = 0; m < 36; m++) {
            float s = 0.f;
            #pragma unroll
            for (int d = 0; d < 8; d++)
                s = fmaf(qv[d], sQ[m * SQ_STRIDE + 64 + qo + d], s);
            sc[m] = s;
            mx = fmaxf(mx, s);
        }
        float sum = 0.f;
        for (int m = 0; m < 36; m++) { float e = expf(sc[m] - mx); sc[m] = e; sum += e; }
        float inv = 1.f / sum;
        float o[8];
        #pragma unroll
        for (int d = 0; d < 8; d++) o[d] = 0.f;
        for (int m = 0; m < 36; m++) {
            float a = sc[m];
            #pragma unroll
            for (int d = 0; d < 8; d++)
                o[d] = fmaf(a, sQ[m * SQ_STRIDE + 128 + qo + d], o[d]);
        }
        #pragma unroll
        for (int d = 0; d < 8; d++) sA[l * SA_STRIDE + qo + d] = o[d] * inv;
    }
    __syncthreads();

    {
        const int l  = tid % 36;
        const int j0 = tid / 36;
        const float* orow = sA + l * SA_STRIDE;
        for (int k = 0; k < 8; k++) {
            int j = j0 + 8 * k;
            float acc = b_out[j];
            const float* wr = w_out + j * 64;
            #pragma unroll
            for (int i = 0; i < 64; i++) acc = fmaf(orow[i], wr[i], acc);
            sQ[l * SK_STRIDE + j] = acc;
        }
    }
    __syncthreads();

    if (tid < 256) {
        int w = tid >> 6, i = tid & 63;
        float s = 0.f;
        #pragma unroll
        for (int p = 0; p < 9; p++) s += sQ[(w * 9 + p) * SK_STRIDE + i];
        pooled[w][i] = s * (1.f / 9.f);
    }
    __syncthreads();
    if (tid < 16) {
        int w = tid >> 2, r = tid & 3;
        float acc = se_b1[w * 4 + r];
        #pragma unroll
        for (int i = 0; i < 64; i++)
            acc = fmaf(pooled[w][i], se_w1[(w * 4 + r) * 64 + i], acc);
        hr[w][r] = fmaxf(acc, 0.f);
    }
    __syncthreads();
    if (tid < 256) {
        int w = tid >> 6, i = tid & 63;   // i = ic
        float acc = se_b2[w * 64 + i];
        #pragma unroll
        for (int r = 0; r < 4; r++)
            acc = fmaf(hr[w][r], se_w2[(w * 64 + i) * 4 + r], acc);
        float g = 1.f / (1.f + expf(-acc));
        #pragma unroll
        for (int p = 0; p < 9; p++) {
            float v = sQ[(w * 9 + p) * SK_STRIDE + i] * g;
            __half hi = __float2half(v);
            __half lo = __float2half(v - __half2float(hi));
            int idx = ((w * 9 + p) * 64 + i) * WROW + b;
            g_Whi[idx] = hi;
            g_Wlo[idx] = lo;
        }
    }
}

// ===========================================================================
// Stage 2: fp16 2-pass WMMA implicit-GEMM conv + LN + residual, taps-outer.
// CTA = 16x16 px tile, 256 threads, 2 CTAs/SM.
// A: full 64-ic halo staged ONCE per CTA (fp32->fp16 converted in-CTA),
//    layout [pos(18*18)][72], lda = 72.
// W: per-tap [64 ic][72 oc] hi+lo, double-buffered via cp.async (overlapped).
// ===========================================================================
#define AROW   72
#define A_ELEMS (324 * AROW)                     // 23328 fp16
#define W_TAP   (64 * WROW)                      // 4608 per hi/lo
#define WBUF_E  (2 * W_TAP)                      // hi+lo per buffer = 9216
#define SMEM2_BYTES ((A_ELEMS + 2 * WBUF_E) * 2) // 83520 B
#define DSTRIDE 68

typedef wmma::fragment<wmma::matrix_a, 16, 16, 16, __half, wmma::row_major> FragA;
typedef wmma::fragment<wmma::matrix_b, 16, 16, 16, __half, wmma::row_major> FragB;
typedef wmma::fragment<wmma::accumulator, 16, 16, 16, float> FragC;

__global__ __launch_bounds__(256, 2) void stage2_kernel(
    const float* __restrict__ x, const float* __restrict__ ln_w,
    const float* __restrict__ ln_b, float* __restrict__ out)
{
    extern __shared__ __half sb[];
    __half* Ash = sb;                            // [324][72]

    const int blk  = blockIdx.x;
    const int tile = blk & 63;
    const int w    = (blk >> 6) & 3;
    const int b    = blk >> 8;
    const int ty0  = (tile >> 3) << 4;
    const int tx0  = (tile & 7) << 4;
    const int wh   = w >> 1, ww = w & 1;

    const int tid = threadIdx.x;
    const int wid = tid >> 5;

    FragC acc[2][4];
    #pragma unroll
    for (int r = 0; r < 2; r++)
        #pragma unroll
        for (int n = 0; n < 4; n++) wmma::fill_fragment(acc[r][n], 0.f);

    // W tap staging into buffer bp (async)
    auto stageW = [&](int p, int bp) {
        const size_t base = (size_t)(w * 9 + p) * W_TAP;
        __half* Wb = sb + A_ELEMS + bp * WBUF_E;
        for (int t = tid; t < 1152; t += 256) {          // 1152 = 2*4608/8
            int hl  = t >= 576;
            int e8  = (hl ? t - 576 : t) * 8;
            cp16(smem_u32(Wb + hl * W_TAP + e8),
                 (hl ? g_Wlo : g_Whi) + base + e8);
        }
    };

    // ---- prologue: W(0) async + full A halo convert (fp32 -> fp16) ----
    stageW(0, 0);
    CP_COMMIT();
    {
        const float* xb = x + (size_t)b * (64 * 65536);
        // pos-major so consecutive lanes hit consecutive x addresses
        for (int i = tid; i < 324 * 64; i += 256) {
            int ic  = i / 324;
            int pos = i - ic * 324;
            int hrow = pos / 18, hcol = pos - hrow * 18;
            int ly = ty0 + hrow - 1, lx = tx0 + hcol - 1;
            float v = 0.f;
            if (ly >= 0 && ly < 128 && lx >= 0 && lx < 128)
                v = xb[(size_t)ic * 65536 + (wh * 128 + ly) * 256 + ww * 128 + lx];
            Ash[pos * AROW + ic] = __float2half(v);
        }
    }
    CP_WAIT0();
    __syncthreads();

    // ---- mainloop: 9 taps outer, 4 ic k-steps inner ----
    #pragma unroll 1
    for (int p = 0; p < 9; p++) {
        if (p < 8) { stageW(p + 1, (p + 1) & 1); CP_COMMIT(); }

        const int dy = p / 3, dx = p - 3 * dy;
        const __half* Whi = sb + A_ELEMS + (p & 1) * WBUF_E;
        const __half* Wlo = Whi + W_TAP;

        #pragma unroll
        for (int kc = 0; kc < 4; kc++) {
            FragB bh[4], bl[4];
            FragA af[2];
            const __half* wbh = Whi + (kc * 16) * WROW;
            const __half* wbl = Wlo + (kc * 16) * WROW;
            #pragma unroll
            for (int n = 0; n < 4; n++) {
                wmma::load_matrix_sync(bh[n], wbh + n * 16, WROW);
                wmma::load_matrix_sync(bl[n], wbl + n * 16, WROW);
            }
            #pragma unroll
            for (int r = 0; r < 2; r++) {
                const int aoff = ((wid * 2 + r + dy) * 18 + dx) * AROW + kc * 16;
                wmma::load_matrix_sync(af[r], Ash + aoff, AROW);
            }
            // pass-outer: each acc reused 8 mmas apart
            #pragma unroll
            for (int r = 0; r < 2; r++)
                #pragma unroll
                for (int n = 0; n < 4; n++)
                    wmma::mma_sync(acc[r][n], af[r], bh[n], acc[r][n]);
            #pragma unroll
            for (int r = 0; r < 2; r++)
                #pragma unroll
                for (int n = 0; n < 4; n++)
                    wmma::mma_sync(acc[r][n], af[r], bl[n], acc[r][n]);
        }
        if (p < 8) CP_WAIT0();
        __syncthreads();
    }

    // ---- epilogue: dump to smem, LN over oc, residual, store ----
    float* D = (float*)sb;                           // [256 px][68]
    #pragma unroll
    for (int r = 0; r < 2; r++) {
        const int yrow = wid * 2 + r;
        #pragma unroll
        for (int n = 0; n < 4; n++)
            wmma::store_matrix_sync(D + (yrow * 16) * DSTRIDE + n * 16,
                                    acc[r][n], DSTRIDE, wmma::mem_row_major);
    }
    __syncthreads();

    {
        const int y  = tid >> 4, xq = tid & 15;
        const float* drow = D + tid * DSTRIDE;
        float s = 0.f, sq = 0.f;
        #pragma unroll
        for (int oc = 0; oc < 64; oc++) {
            float d = drow[oc];
            s += d;
            sq = fmaf(d, d, sq);
        }
        float mu   = s * (1.f / 64.f);
        float rstd = rsqrtf(sq * (1.f / 64.f) - mu * mu + 1e-5f);
        const int gy = wh * 128 + ty0 + y;
        const int gx = ww * 128 + tx0 + xq;
        #pragma unroll 4
        for (int oc = 0; oc < 64; oc++) {
            size_t gi = ((size_t)(b * 64 + oc) * 256 + gy) * 256 + gx;
            out[gi] = x[gi] + (drow[oc] - mu) * rstd * ln_w[oc] + ln_b[oc];
        }
    }
}

// ===========================================================================
extern "C" void kernel_launch(void* const* d_in, const int* in_sizes, int n_in,
                              void* d_out, int out_size)
{
    (void)in_sizes; (void)n_in; (void)out_size;
    const float* x      = (const float*)d_in[0];
    const float* conv_w = (const float*)d_in[1];
    const float* w_qkv  = (const float*)d_in[2];
    const float* b_qkv  = (const float*)d_in[3];
    const float* w_out  = (const float*)d_in[4];
    const float* b_out  = (const float*)d_in[5];
    const float* se_w1  = (const float*)d_in[6];
    const float* se_b1  = (const float*)d_in[7];
    const float* se_w2  = (const float*)d_in[8];
    const float* se_b2  = (const float*)d_in[9];
    const float* ln_w   = (const float*)d_in[10];
    const float* ln_b   = (const float*)d_in[11];
    float* out = (float*)d_out;

    cudaFuncSetAttribute(stage2_kernel,
                         cudaFuncAttributeMaxDynamicSharedMemorySize, SMEM2_BYTES);

    stage1_kernel<<<64, 288>>>(conv_w, w_qkv, b_qkv, w_out, b_out,
                               se_w1, se_b1, se_w2, se_b2);
    stage2_kernel<<<2048, 256, SMEM2_BYTES>>>(x, ln_w, ln_b, out);
}